// round 9
// baseline (speedup 1.0000x reference)
#include <cuda_runtime.h>
#include <cstdint>
#include <mma.h>
#include <math.h>

using namespace nvcuda;

#define BATCH   8
#define L_SEQ   680
#define NHEADS  24
#define HDIM    64
#define CDIM    1536
#define MROWS   (BATCH * L_SEQ)      // 5440
#define QKVN    (3 * CDIM)           // 4608
#define SM_STRIDE 68

// ---------------- GEMM tiling (legacy tf32 HMMA, Ampere-compatible) --------
#define GBM 128
#define GBN 128
#define GBK 32
#define NSTAGE 3
#define TLD 36                         // 32 + 4 pad (floats)
#define STAGE_F (2 * GBM * TLD)        // floats per stage (A tile + B tile)
#define EPLD 132
#define GEMM_THREADS 128
#define GEMM_SMEM_BYTES (NSTAGE * STAGE_F * 4)   // 110592

__device__ float g_qkv[MROWS * QKVN];   // raw qkv (pre-RoPE), fp32
__device__ float g_ao [MROWS * CDIM];   // attention output (tf32-rounded)
__device__ float g_bias[QKVN];
__device__ float g_xr   [MROWS * CDIM];
__device__ float g_wqkvr[QKVN * CDIM];
__device__ float g_wor  [CDIM * CDIM];

// ---------------------------------------------------------------------------
__global__ void bias_compose_kernel(const float* __restrict__ qb,
                                    const float* __restrict__ vb) {
    int n = blockIdx.x * 256 + threadIdx.x;
    if (n >= QKVN) return;
    float v = 0.f;
    if (n < CDIM)            v = qb[n];
    else if (n >= 2 * CDIM)  v = vb[n - 2 * CDIM];
    g_bias[n] = v;
}

__global__ __launch_bounds__(256) void round_tf32_kernel(
    const float* __restrict__ x, float* __restrict__ y, int n4)
{
    int i = blockIdx.x * 256 + threadIdx.x;
    if (i >= n4) return;
    float4 v = ((const float4*)x)[i];
    v.x = wmma::__float_to_tf32(v.x);
    v.y = wmma::__float_to_tf32(v.y);
    v.z = wmma::__float_to_tf32(v.z);
    v.w = wmma::__float_to_tf32(v.w);
    ((float4*)y)[i] = v;
}

// ---------------------------------------------------------------------------
__device__ __forceinline__ void cp_async16(float* smem, const float* g, bool pred) {
    unsigned int saddr = (unsigned int)__cvta_generic_to_shared(smem);
    int sz = pred ? 16 : 0;
    asm volatile("cp.async.cg.shared.global [%0], [%1], 16, %2;\n"
                 :: "r"(saddr), "l"(g), "r"(sz));
}
__device__ __forceinline__ void cp_commit() {
    asm volatile("cp.async.commit_group;\n");
}
template <int N>
__device__ __forceinline__ void cp_wait() {
    asm volatile("cp.async.wait_group %0;\n" :: "n"(N));
}

// ---------------------------------------------------------------------------
// C[m][n] = sum_k A[m][k] * Bm[n][k] + bias[n]   (tf32 HMMA)
// CTA 128x128x32, 4 warps, warp tile 64x64, 3-stage cp.async ring,
// ONE __syncthreads per k-tile. A/Bm must be tf32-pre-rounded.
// ---------------------------------------------------------------------------
__global__ __launch_bounds__(GEMM_THREADS) void gemm_tf32_bt_bias(
    const float* __restrict__ A, const float* __restrict__ Bm,
    const float* __restrict__ bias, float* __restrict__ C,
    int M, int N, int K)
{
    extern __shared__ float sm[];

    const int tid = threadIdx.x;
    const int wid = tid >> 5;
    const int m0  = blockIdx.y * GBM;
    const int n0  = blockIdx.x * GBN;
    const int wm  = wid >> 1;          // 0..1 : row block (64)
    const int wn  = wid & 1;           // 0..1 : col block (64)

    // load mapping: each thread owns one row (A row tid, B row tid), 8 float4s
    const bool arow_ok = (m0 + tid) < M;
    const float* Ag = A  + (size_t)(m0 + tid) * K;
    const float* Bg = Bm + (size_t)(n0 + tid) * K;

    wmma::fragment<wmma::accumulator, 16, 16, 8, float> acc[4][4];
    #pragma unroll
    for (int i = 0; i < 4; i++)
        #pragma unroll
        for (int j = 0; j < 4; j++)
            wmma::fill_fragment(acc[i][j], 0.0f);

    const int nk = K / GBK;

    // stage loader: A[128][32] + B[128][32] into stage s at k-offset kc
    auto load_stage = [&](int s, int kc) {
        float* a_dst = sm + s * STAGE_F + tid * TLD;
        float* b_dst = a_dst + GBM * TLD;
        #pragma unroll
        for (int c = 0; c < 8; c++) {
            cp_async16(a_dst + c * 4, Ag + kc + c * 4, arow_ok);
            cp_async16(b_dst + c * 4, Bg + kc + c * 4, true);
        }
    };

    load_stage(0, 0);        cp_commit();
    load_stage(1, GBK);      cp_commit();

    for (int kt = 0; kt < nk; kt++) {
        cp_wait<1>();
        __syncthreads();     // stage kt ready for all; all done computing kt-1

        if (kt + 2 < nk) {   // overwrite buffer (kt+2)%3 == (kt-1)%3 — safe
            load_stage((kt + 2) % NSTAGE, (kt + 2) * GBK);
            cp_commit();
        }

        const float* ab = sm + (kt % NSTAGE) * STAGE_F;
        const float* bb = ab + GBM * TLD;

        #pragma unroll
        for (int ks = 0; ks < 4; ks++) {
            wmma::fragment<wmma::matrix_a, 16, 16, 8, wmma::precision::tf32,
                           wmma::row_major> af[4];
            wmma::fragment<wmma::matrix_b, 16, 16, 8, wmma::precision::tf32,
                           wmma::col_major> bf[4];
            #pragma unroll
            for (int i = 0; i < 4; i++)
                wmma::load_matrix_sync(af[i],
                    ab + (wm * 64 + i * 16) * TLD + ks * 8, TLD);
            #pragma unroll
            for (int j = 0; j < 4; j++)
                wmma::load_matrix_sync(bf[j],
                    bb + (wn * 64 + j * 16) * TLD + ks * 8, TLD);
            #pragma unroll
            for (int i = 0; i < 4; i++)
                #pragma unroll
                for (int j = 0; j < 4; j++)
                    wmma::mma_sync(acc[i][j], af[i], bf[j], acc[i][j]);
        }
    }

    // epilogue: stage full 128x128 tile in smem, add bias, write out
    __syncthreads();
    #pragma unroll
    for (int i = 0; i < 4; i++)
        #pragma unroll
        for (int j = 0; j < 4; j++)
            wmma::store_matrix_sync(
                sm + (wm * 64 + i * 16) * EPLD + wn * 64 + j * 16,
                acc[i][j], EPLD, wmma::mem_row_major);
    __syncthreads();

    if ((m0 + tid) < M) {
        float* cp = C + (size_t)(m0 + tid) * N + n0;
        const float* ep = sm + tid * EPLD;
        const float* bp = bias + n0;
        #pragma unroll
        for (int j = 0; j < 32; j++) {
            float4 v = *(const float4*)(ep + j * 4);
            v.x += bp[j * 4 + 0]; v.y += bp[j * 4 + 1];
            v.z += bp[j * 4 + 2]; v.w += bp[j * 4 + 3];
            *(float4*)(cp + j * 4) = v;
        }
    }
}

// ---------------------------------------------------------------------------
// Flash attention with RoPE applied on-the-fly (fp32 FFMA)
// Output ao is tf32-rounded (so the 2nd GEMM needs no conversion).
// ---------------------------------------------------------------------------
__device__ __forceinline__ void load_rope_tile(
    float (*dstT)[SM_STRIDE], const float* __restrict__ pos,
    int b, int h, int row_base, int comp_off, int tid)
{
    for (int u = tid; u < 512; u += 256) {
        int row = u >> 3;
        int d   = (u & 7) * 4;          // d in [0,32)
        int lg  = row_base + row;
        float4 va = {0,0,0,0}, vb = {0,0,0,0};
        float p0 = 0.f, p1 = 0.f;
        if (lg < L_SEQ) {
            const float* src = g_qkv + (size_t)(b * L_SEQ + lg) * QKVN
                               + comp_off + h * HDIM;
            va = *(const float4*)(src + d);
            vb = *(const float4*)(src + d + 32);
            p0 = pos[(size_t)(b * L_SEQ + lg) * 2 + 0];
            p1 = pos[(size_t)(b * L_SEQ + lg) * 2 + 1];
        }
        const float* xa = (const float*)&va;
        const float* xb = (const float*)&vb;
        #pragma unroll
        for (int j = 0; j < 4; j++) {
            int fi = (d + j) & 15;
            float invf = __expf(-0.5756462732485115f * (float)fi); // 10000^(-fi/16)
            float sa, ca, sb, cb;
            __sincosf(p0 * invf, &sa, &ca);
            __sincosf(p1 * invf, &sb, &cb);
            dstT[d + j][row]      = xa[j] * ca - xb[j] * sa;
            dstT[d + 32 + j][row] = xb[j] * cb + xa[j] * sb;
        }
    }
}

__global__ __launch_bounds__(256) void attn_kernel(
    const float* __restrict__ pos, float* __restrict__ ao)
{
    extern __shared__ float smf[];
    float (*QsT)[SM_STRIDE] = (float(*)[SM_STRIDE])(smf);
    float (*KsT)[SM_STRIDE] = (float(*)[SM_STRIDE])(smf + 64*SM_STRIDE);
    float (*Vs )[SM_STRIDE] = (float(*)[SM_STRIDE])(smf + 2*64*SM_STRIDE);
    float (*PsT)[SM_STRIDE] = (float(*)[SM_STRIDE])(smf + 3*64*SM_STRIDE);

    int qt = blockIdx.x, h = blockIdx.y, b = blockIdx.z;
    int tid = threadIdx.x;
    int ty = tid >> 4, tx = tid & 15;
    int q0 = qt * 64;

    load_rope_tile(QsT, pos, b, h, q0, 0, tid);

    float O[4][4] = {};
    float mrun[4], lrun[4];
    #pragma unroll
    for (int i = 0; i < 4; i++) { mrun[i] = -1e30f; lrun[i] = 0.f; }

    const int NT = (L_SEQ + 63) / 64;   // 11
    for (int kt = 0; kt < NT; kt++) {
        int k0 = kt * 64;
        __syncthreads();

        load_rope_tile(KsT, pos, b, h, k0, CDIM, tid);
        for (int u = tid; u < 1024; u += 256) {
            int row = u >> 4, c4 = (u & 15) << 2;
            int lg = k0 + row;
            float4 v = {0,0,0,0};
            if (lg < L_SEQ)
                v = *(const float4*)(g_qkv + (size_t)(b*L_SEQ + lg)*QKVN
                                     + 2*CDIM + h*HDIM + c4);
            *(float4*)&Vs[row][c4] = v;
        }
        __syncthreads();

        float sacc[4][4] = {};
        #pragma unroll 8
        for (int d = 0; d < 64; d++) {
            float4 a  = *(const float4*)&QsT[d][ty*4];
            float4 bq = *(const float4*)&KsT[d][tx*4];
            float av[4] = {a.x, a.y, a.z, a.w};
            float bv[4] = {bq.x, bq.y, bq.z, bq.w};
            #pragma unroll
            for (int i = 0; i < 4; i++)
                #pragma unroll
                for (int j = 0; j < 4; j++)
                    sacc[i][j] = fmaf(av[i], bv[j], sacc[i][j]);
        }
        #pragma unroll
        for (int i = 0; i < 4; i++)
            #pragma unroll
            for (int j = 0; j < 4; j++) {
                float s = sacc[i][j] * 0.125f;
                if (k0 + tx*4 + j >= L_SEQ) s = -1e30f;
                sacc[i][j] = s;
            }

        #pragma unroll
        for (int i = 0; i < 4; i++) {
            float mx = fmaxf(fmaxf(sacc[i][0], sacc[i][1]),
                             fmaxf(sacc[i][2], sacc[i][3]));
            #pragma unroll
            for (int off = 8; off >= 1; off >>= 1)
                mx = fmaxf(mx, __shfl_xor_sync(0xffffffffu, mx, off, 16));
            float m_new = fmaxf(mrun[i], mx);
            float alpha = __expf(mrun[i] - m_new);
            float rsum = 0.f;
            #pragma unroll
            for (int j = 0; j < 4; j++) {
                float p = __expf(sacc[i][j] - m_new);
                sacc[i][j] = p;
                rsum += p;
            }
            #pragma unroll
            for (int off = 8; off >= 1; off >>= 1)
                rsum += __shfl_xor_sync(0xffffffffu, rsum, off, 16);
            lrun[i] = lrun[i] * alpha + rsum;
            mrun[i] = m_new;
            #pragma unroll
            for (int j = 0; j < 4; j++) O[i][j] *= alpha;
            #pragma unroll
            for (int j = 0; j < 4; j++) PsT[tx*4 + j][ty*4 + i] = sacc[i][j];
        }
        __syncthreads();

        #pragma unroll 8
        for (int j = 0; j < 64; j++) {
            float4 a  = *(const float4*)&PsT[j][ty*4];
            float4 v4 = *(const float4*)&Vs[j][tx*4];
            float av[4] = {a.x, a.y, a.z, a.w};
            float vv[4] = {v4.x, v4.y, v4.z, v4.w};
            #pragma unroll
            for (int i = 0; i < 4; i++)
                #pragma unroll
                for (int jj = 0; jj < 4; jj++)
                    O[i][jj] = fmaf(av[i], vv[jj], O[i][jj]);
        }
    }

    #pragma unroll
    for (int i = 0; i < 4; i++) {
        int lg = q0 + ty*4 + i;
        if (lg < L_SEQ) {
            float inv_l = 1.0f / lrun[i];
            float4 o4 = make_float4(
                wmma::__float_to_tf32(O[i][0]*inv_l),
                wmma::__float_to_tf32(O[i][1]*inv_l),
                wmma::__float_to_tf32(O[i][2]*inv_l),
                wmma::__float_to_tf32(O[i][3]*inv_l));
            *(float4*)(ao + (size_t)(b*L_SEQ + lg)*CDIM + h*HDIM + tx*4) = o4;
        }
    }
}

// ---------------------------------------------------------------------------
extern "C" void kernel_launch(void* const* d_in, const int* in_sizes, int n_in,
                              void* d_out, int out_size)
{
    const float* x    = (const float*)d_in[0];
    const float* pos  = (const float*)d_in[1];
    const float* wqkv = (const float*)d_in[2];
    const float* qb   = (const float*)d_in[3];
    const float* vb   = (const float*)d_in[4];
    const float* wo   = (const float*)d_in[5];
    const float* bo   = (const float*)d_in[6];
    float* out = (float*)d_out;

    float *qkv_p, *ao_p, *bias_p, *xr_p, *wqkvr_p, *wor_p;
    cudaGetSymbolAddress((void**)&qkv_p,   g_qkv);
    cudaGetSymbolAddress((void**)&ao_p,    g_ao);
    cudaGetSymbolAddress((void**)&bias_p,  g_bias);
    cudaGetSymbolAddress((void**)&xr_p,    g_xr);
    cudaGetSymbolAddress((void**)&wqkvr_p, g_wqkvr);
    cudaGetSymbolAddress((void**)&wor_p,   g_wor);

    bias_compose_kernel<<<(QKVN + 255)/256, 256>>>(qb, vb);

    // pre-round operands to tf32 (keeps GEMM mainloop CVT-free)
    {
        int n4 = (MROWS * CDIM) / 4;
        round_tf32_kernel<<<(n4 + 255)/256, 256>>>(x, xr_p, n4);
        n4 = (QKVN * CDIM) / 4;
        round_tf32_kernel<<<(n4 + 255)/256, 256>>>(wqkv, wqkvr_p, n4);
        n4 = (CDIM * CDIM) / 4;
        round_tf32_kernel<<<(n4 + 255)/256, 256>>>(wo, wor_p, n4);
    }

    cudaFuncSetAttribute(gemm_tf32_bt_bias,
                         cudaFuncAttributeMaxDynamicSharedMemorySize, GEMM_SMEM_BYTES);

    dim3 g1(QKVN / GBN, (MROWS + GBM - 1) / GBM);
    gemm_tf32_bt_bias<<<g1, GEMM_THREADS, GEMM_SMEM_BYTES>>>(
        xr_p, wqkvr_p, bias_p, qkv_p, MROWS, QKVN, CDIM);

    int smem_attn = 4 * 64 * SM_STRIDE * (int)sizeof(float);   // 69632
    cudaFuncSetAttribute(attn_kernel,
                         cudaFuncAttributeMaxDynamicSharedMemorySize, smem_attn);
    attn_kernel<<<dim3((L_SEQ + 63)/64, NHEADS, BATCH), 256, smem_attn>>>(pos, ao_p);

    dim3 g2(CDIM / GBN, (MROWS + GBM - 1) / GBM);
    gemm_tf32_bt_bias<<<g2, GEMM_THREADS, GEMM_SMEM_BYTES>>>(
        ao_p, wor_p, bo, out, MROWS, CDIM, CDIM);
}

// round 10
// speedup vs baseline: 1.8266x; 1.8266x over previous
#include <cuda_runtime.h>
#include <cstdint>
#include <mma.h>
#include <math.h>

using namespace nvcuda;

#define BATCH   8
#define L_SEQ   680
#define NHEADS  24
#define HDIM    64
#define CDIM    1536
#define MROWS   (BATCH * L_SEQ)      // 5440
#define QKVN    (3 * CDIM)           // 4608
#define SM_STRIDE 68

// ---------------- GEMM tiling (legacy tf32 HMMA) ---------------------------
// CTA tile 256x128x32, 8 warps (2x4: wm 0..3 over 256 rows, wn 0..1 over 128
// cols), warp tile 64x64, 3-stage cp.async ring, one __syncthreads per k-tile.
#define GBM 256
#define GBN 128
#define GBK 32
#define NSTAGE 3
#define TLD 36                          // 32 + 4 pad (floats)
#define SROWS (GBM + GBN)               // 384 rows per stage (A then B)
#define STAGE_F (SROWS * TLD)           // 13824 floats per stage
#define EPLD 132
#define GEMM_THREADS 256
#define GEMM_SMEM_BYTES (NSTAGE * STAGE_F * 4)   // 165888

__device__ float g_qkv[MROWS * QKVN];   // raw qkv (pre-RoPE), fp32
__device__ float g_ao [MROWS * CDIM];   // attention output (tf32-rounded)
__device__ float g_bias[QKVN];
__device__ float g_xr   [MROWS * CDIM];
__device__ float g_wqkvr[QKVN * CDIM];
__device__ float g_wor  [CDIM * CDIM];

// ---------------------------------------------------------------------------
__global__ void bias_compose_kernel(const float* __restrict__ qb,
                                    const float* __restrict__ vb) {
    int n = blockIdx.x * 256 + threadIdx.x;
    if (n >= QKVN) return;
    float v = 0.f;
    if (n < CDIM)            v = qb[n];
    else if (n >= 2 * CDIM)  v = vb[n - 2 * CDIM];
    g_bias[n] = v;
}

__global__ __launch_bounds__(256) void round_tf32_kernel(
    const float* __restrict__ x, float* __restrict__ y, int n4)
{
    int i = blockIdx.x * 256 + threadIdx.x;
    if (i >= n4) return;
    float4 v = ((const float4*)x)[i];
    v.x = wmma::__float_to_tf32(v.x);
    v.y = wmma::__float_to_tf32(v.y);
    v.z = wmma::__float_to_tf32(v.z);
    v.w = wmma::__float_to_tf32(v.w);
    ((float4*)y)[i] = v;
}

// ---------------------------------------------------------------------------
__device__ __forceinline__ void cp_async16(float* smem, const float* g, bool pred) {
    unsigned int saddr = (unsigned int)__cvta_generic_to_shared(smem);
    int sz = pred ? 16 : 0;
    asm volatile("cp.async.cg.shared.global [%0], [%1], 16, %2;\n"
                 :: "r"(saddr), "l"(g), "r"(sz));
}
__device__ __forceinline__ void cp_commit() {
    asm volatile("cp.async.commit_group;\n");
}
template <int N>
__device__ __forceinline__ void cp_wait() {
    asm volatile("cp.async.wait_group %0;\n" :: "n"(N));
}

// ---------------------------------------------------------------------------
// C[m][n] = sum_k A[m][k] * Bm[n][k] + bias[n]   (tf32 HMMA)
// A/Bm must be tf32-pre-rounded.
// ---------------------------------------------------------------------------
__global__ __launch_bounds__(GEMM_THREADS) void gemm_tf32_bt_bias(
    const float* __restrict__ A, const float* __restrict__ Bm,
    const float* __restrict__ bias, float* __restrict__ C,
    int M, int N, int K)
{
    extern __shared__ float sm[];

    const int tid = threadIdx.x;
    const int wid = tid >> 5;
    const int m0  = blockIdx.y * GBM;
    const int n0  = blockIdx.x * GBN;
    const int wm  = wid >> 1;          // 0..3 : 64-row block
    const int wn  = wid & 1;           // 0..1 : 64-col block

    wmma::fragment<wmma::accumulator, 16, 16, 8, float> acc[4][4];
    #pragma unroll
    for (int i = 0; i < 4; i++)
        #pragma unroll
        for (int j = 0; j < 4; j++)
            wmma::fill_fragment(acc[i][j], 0.0f);

    const int nk = K / GBK;

    // stage loader: A[256][32] rows 0..255, B[128][32] rows 256..383
    // 3072 float4s, 12 per thread. Each r-block is row-uniform (A vs B).
    auto load_stage = [&](int s, int kc) {
        float* base = sm + s * STAGE_F;
        #pragma unroll
        for (int r = 0; r < 12; r++) {
            int u    = tid + r * GEMM_THREADS;   // 0..3071
            int row  = u >> 3;
            int slot = u & 7;
            float* dst = base + row * TLD + slot * 4;
            if (row < GBM) {
                cp_async16(dst, A + (size_t)(m0 + row) * K + kc + slot * 4,
                           (m0 + row) < M);
            } else {
                cp_async16(dst, Bm + (size_t)(n0 + row - GBM) * K + kc + slot * 4,
                           true);
            }
        }
    };

    load_stage(0, 0);        cp_commit();
    load_stage(1, GBK);      cp_commit();

    for (int kt = 0; kt < nk; kt++) {
        cp_wait<1>();
        __syncthreads();     // stage kt ready; all warps done with kt-1

        if (kt + 2 < nk) {   // buffer (kt+2)%3 == (kt-1)%3 — safe to overwrite
            load_stage((kt + 2) % NSTAGE, (kt + 2) * GBK);
            cp_commit();
        }

        const float* ab = sm + (kt % NSTAGE) * STAGE_F;
        const float* bb = ab + GBM * TLD;

        #pragma unroll
        for (int ks = 0; ks < 4; ks++) {
            wmma::fragment<wmma::matrix_a, 16, 16, 8, wmma::precision::tf32,
                           wmma::row_major> af[4];
            wmma::fragment<wmma::matrix_b, 16, 16, 8, wmma::precision::tf32,
                           wmma::col_major> bf[4];
            #pragma unroll
            for (int i = 0; i < 4; i++)
                wmma::load_matrix_sync(af[i],
                    ab + (wm * 64 + i * 16) * TLD + ks * 8, TLD);
            #pragma unroll
            for (int j = 0; j < 4; j++)
                wmma::load_matrix_sync(bf[j],
                    bb + (wn * 64 + j * 16) * TLD + ks * 8, TLD);
            #pragma unroll
            for (int i = 0; i < 4; i++)
                #pragma unroll
                for (int j = 0; j < 4; j++)
                    wmma::mma_sync(acc[i][j], af[i], bf[j], acc[i][j]);
        }
    }

    // epilogue: stage full 256x128 tile in smem (135KB < alloc), bias, write
    __syncthreads();
    #pragma unroll
    for (int i = 0; i < 4; i++)
        #pragma unroll
        for (int j = 0; j < 4; j++)
            wmma::store_matrix_sync(
                sm + (wm * 64 + i * 16) * EPLD + wn * 64 + j * 16,
                acc[i][j], EPLD, wmma::mem_row_major);
    __syncthreads();

    if ((m0 + tid) < M) {
        float* cp = C + (size_t)(m0 + tid) * N + n0;
        const float* ep = sm + tid * EPLD;
        const float* bp = bias + n0;
        #pragma unroll
        for (int j = 0; j < 32; j++) {
            float4 v = *(const float4*)(ep + j * 4);
            v.x += bp[j * 4 + 0]; v.y += bp[j * 4 + 1];
            v.z += bp[j * 4 + 2]; v.w += bp[j * 4 + 3];
            *(float4*)(cp + j * 4) = v;
        }
    }
}

// ---------------------------------------------------------------------------
// Flash attention with RoPE applied on-the-fly (fp32 FFMA)
// Output ao is tf32-rounded (so the 2nd GEMM needs no conversion).
// ---------------------------------------------------------------------------
__device__ __forceinline__ void load_rope_tile(
    float (*dstT)[SM_STRIDE], const float* __restrict__ pos,
    int b, int h, int row_base, int comp_off, int tid)
{
    for (int u = tid; u < 512; u += 256) {
        int row = u >> 3;
        int d   = (u & 7) * 4;          // d in [0,32)
        int lg  = row_base + row;
        float4 va = {0,0,0,0}, vb = {0,0,0,0};
        float p0 = 0.f, p1 = 0.f;
        if (lg < L_SEQ) {
            const float* src = g_qkv + (size_t)(b * L_SEQ + lg) * QKVN
                               + comp_off + h * HDIM;
            va = *(const float4*)(src + d);
            vb = *(const float4*)(src + d + 32);
            p0 = pos[(size_t)(b * L_SEQ + lg) * 2 + 0];
            p1 = pos[(size_t)(b * L_SEQ + lg) * 2 + 1];
        }
        const float* xa = (const float*)&va;
        const float* xb = (const float*)&vb;
        #pragma unroll
        for (int j = 0; j < 4; j++) {
            int fi = (d + j) & 15;
            float invf = __expf(-0.5756462732485115f * (float)fi); // 10000^(-fi/16)
            float sa, ca, sb, cb;
            __sincosf(p0 * invf, &sa, &ca);
            __sincosf(p1 * invf, &sb, &cb);
            dstT[d + j][row]      = xa[j] * ca - xb[j] * sa;
            dstT[d + 32 + j][row] = xb[j] * cb + xa[j] * sb;
        }
    }
}

__global__ __launch_bounds__(256) void attn_kernel(
    const float* __restrict__ pos, float* __restrict__ ao)
{
    extern __shared__ float smf[];
    float (*QsT)[SM_STRIDE] = (float(*)[SM_STRIDE])(smf);
    float (*KsT)[SM_STRIDE] = (float(*)[SM_STRIDE])(smf + 64*SM_STRIDE);
    float (*Vs )[SM_STRIDE] = (float(*)[SM_STRIDE])(smf + 2*64*SM_STRIDE);
    float (*PsT)[SM_STRIDE] = (float(*)[SM_STRIDE])(smf + 3*64*SM_STRIDE);

    int qt = blockIdx.x, h = blockIdx.y, b = blockIdx.z;
    int tid = threadIdx.x;
    int ty = tid >> 4, tx = tid & 15;
    int q0 = qt * 64;

    load_rope_tile(QsT, pos, b, h, q0, 0, tid);

    float O[4][4] = {};
    float mrun[4], lrun[4];
    #pragma unroll
    for (int i = 0; i < 4; i++) { mrun[i] = -1e30f; lrun[i] = 0.f; }

    const int NT = (L_SEQ + 63) / 64;   // 11
    for (int kt = 0; kt < NT; kt++) {
        int k0 = kt * 64;
        __syncthreads();

        load_rope_tile(KsT, pos, b, h, k0, CDIM, tid);
        for (int u = tid; u < 1024; u += 256) {
            int row = u >> 4, c4 = (u & 15) << 2;
            int lg = k0 + row;
            float4 v = {0,0,0,0};
            if (lg < L_SEQ)
                v = *(const float4*)(g_qkv + (size_t)(b*L_SEQ + lg)*QKVN
                                     + 2*CDIM + h*HDIM + c4);
            *(float4*)&Vs[row][c4] = v;
        }
        __syncthreads();

        float sacc[4][4] = {};
        #pragma unroll 8
        for (int d = 0; d < 64; d++) {
            float4 a  = *(const float4*)&QsT[d][ty*4];
            float4 bq = *(const float4*)&KsT[d][tx*4];
            float av[4] = {a.x, a.y, a.z, a.w};
            float bv[4] = {bq.x, bq.y, bq.z, bq.w};
            #pragma unroll
            for (int i = 0; i < 4; i++)
                #pragma unroll
                for (int j = 0; j < 4; j++)
                    sacc[i][j] = fmaf(av[i], bv[j], sacc[i][j]);
        }
        #pragma unroll
        for (int i = 0; i < 4; i++)
            #pragma unroll
            for (int j = 0; j < 4; j++) {
                float s = sacc[i][j] * 0.125f;
                if (k0 + tx*4 + j >= L_SEQ) s = -1e30f;
                sacc[i][j] = s;
            }

        #pragma unroll
        for (int i = 0; i < 4; i++) {
            float mx = fmaxf(fmaxf(sacc[i][0], sacc[i][1]),
                             fmaxf(sacc[i][2], sacc[i][3]));
            #pragma unroll
            for (int off = 8; off >= 1; off >>= 1)
                mx = fmaxf(mx, __shfl_xor_sync(0xffffffffu, mx, off, 16));
            float m_new = fmaxf(mrun[i], mx);
            float alpha = __expf(mrun[i] - m_new);
            float rsum = 0.f;
            #pragma unroll
            for (int j = 0; j < 4; j++) {
                float p = __expf(sacc[i][j] - m_new);
                sacc[i][j] = p;
                rsum += p;
            }
            #pragma unroll
            for (int off = 8; off >= 1; off >>= 1)
                rsum += __shfl_xor_sync(0xffffffffu, rsum, off, 16);
            lrun[i] = lrun[i] * alpha + rsum;
            mrun[i] = m_new;
            #pragma unroll
            for (int j = 0; j < 4; j++) O[i][j] *= alpha;
            #pragma unroll
            for (int j = 0; j < 4; j++) PsT[tx*4 + j][ty*4 + i] = sacc[i][j];
        }
        __syncthreads();

        #pragma unroll 8
        for (int j = 0; j < 64; j++) {
            float4 a  = *(const float4*)&PsT[j][ty*4];
            float4 v4 = *(const float4*)&Vs[j][tx*4];
            float av[4] = {a.x, a.y, a.z, a.w};
            float vv[4] = {v4.x, v4.y, v4.z, v4.w};
            #pragma unroll
            for (int i = 0; i < 4; i++)
                #pragma unroll
                for (int jj = 0; jj < 4; jj++)
                    O[i][jj] = fmaf(av[i], vv[jj], O[i][jj]);
        }
    }

    #pragma unroll
    for (int i = 0; i < 4; i++) {
        int lg = q0 + ty*4 + i;
        if (lg < L_SEQ) {
            float inv_l = 1.0f / lrun[i];
            float4 o4 = make_float4(
                wmma::__float_to_tf32(O[i][0]*inv_l),
                wmma::__float_to_tf32(O[i][1]*inv_l),
                wmma::__float_to_tf32(O[i][2]*inv_l),
                wmma::__float_to_tf32(O[i][3]*inv_l));
            *(float4*)(ao + (size_t)(b*L_SEQ + lg)*CDIM + h*HDIM + tx*4) = o4;
        }
    }
}

// ---------------------------------------------------------------------------
extern "C" void kernel_launch(void* const* d_in, const int* in_sizes, int n_in,
                              void* d_out, int out_size)
{
    const float* x    = (const float*)d_in[0];
    const float* pos  = (const float*)d_in[1];
    const float* wqkv = (const float*)d_in[2];
    const float* qb   = (const float*)d_in[3];
    const float* vb   = (const float*)d_in[4];
    const float* wo   = (const float*)d_in[5];
    const float* bo   = (const float*)d_in[6];
    float* out = (float*)d_out;

    float *qkv_p, *ao_p, *bias_p, *xr_p, *wqkvr_p, *wor_p;
    cudaGetSymbolAddress((void**)&qkv_p,   g_qkv);
    cudaGetSymbolAddress((void**)&ao_p,    g_ao);
    cudaGetSymbolAddress((void**)&bias_p,  g_bias);
    cudaGetSymbolAddress((void**)&xr_p,    g_xr);
    cudaGetSymbolAddress((void**)&wqkvr_p, g_wqkvr);
    cudaGetSymbolAddress((void**)&wor_p,   g_wor);

    bias_compose_kernel<<<(QKVN + 255)/256, 256>>>(qb, vb);

    // pre-round operands to tf32 (keeps GEMM mainloop CVT-free)
    {
        int n4 = (MROWS * CDIM) / 4;
        round_tf32_kernel<<<(n4 + 255)/256, 256>>>(x, xr_p, n4);
        n4 = (QKVN * CDIM) / 4;
        round_tf32_kernel<<<(n4 + 255)/256, 256>>>(wqkv, wqkvr_p, n4);
        n4 = (CDIM * CDIM) / 4;
        round_tf32_kernel<<<(n4 + 255)/256, 256>>>(wo, wor_p, n4);
    }

    cudaFuncSetAttribute(gemm_tf32_bt_bias,
                         cudaFuncAttributeMaxDynamicSharedMemorySize, GEMM_SMEM_BYTES);

    dim3 g1(QKVN / GBN, (MROWS + GBM - 1) / GBM);
    gemm_tf32_bt_bias<<<g1, GEMM_THREADS, GEMM_SMEM_BYTES>>>(
        xr_p, wqkvr_p, bias_p, qkv_p, MROWS, QKVN, CDIM);

    int smem_attn = 4 * 64 * SM_STRIDE * (int)sizeof(float);   // 69632
    cudaFuncSetAttribute(attn_kernel,
                         cudaFuncAttributeMaxDynamicSharedMemorySize, smem_attn);
    attn_kernel<<<dim3((L_SEQ + 63)/64, NHEADS, BATCH), 256, smem_attn>>>(pos, ao_p);

    dim3 g2(CDIM / GBN, (MROWS + GBM - 1) / GBM);
    gemm_tf32_bt_bias<<<g2, GEMM_THREADS, GEMM_SMEM_BYTES>>>(
        ao_p, wor_p, bo, out, MROWS, CDIM, CDIM);
}